// round 15
// baseline (speedup 1.0000x reference)
#include <cuda_runtime.h>
#include <cuda_fp16.h>
#include <math.h>
#include <cstdint>

#define BATCH 2
#define TSEQ  2048
#define CDIM  1024
#define NHEAD 16
#define HDIM  64
#define MROWS (BATCH*TSEQ)          // 4096
#define QKV_N (3*CDIM)              // 3072

// Scratch (no runtime allocation allowed)
__device__ __half g_qkvh[MROWS * QKV_N];    // [B*T, 3C] half
__device__ __half g_yh  [MROWS * CDIM];     // [B*T, C]  half (attn out)
__device__ __half g_xh  [MROWS * CDIM];     // half copy of x
__device__ __half g_wtq [QKV_N * CDIM];     // W_qkv^T half
__device__ __half g_wto [CDIM * CDIM];      // W_o^T   half

// ---------------------------------------------------------------------------
// helpers
// ---------------------------------------------------------------------------
__device__ __forceinline__ uint32_t smem_u32(const void* p) {
    uint32_t a;
    asm("{ .reg .u64 t; cvta.to.shared.u64 t, %1; cvt.u32.u64 %0, t; }" : "=r"(a) : "l"(p));
    return a;
}
#define CP_ASYNC16(dst, src) \
    asm volatile("cp.async.cg.shared.global [%0], [%1], 16;" :: "r"(dst), "l"(src) : "memory")
#define CP_COMMIT() asm volatile("cp.async.commit_group;" ::: "memory")
#define CP_WAIT(n)  asm volatile("cp.async.wait_group %0;" :: "n"(n) : "memory")

__device__ __forceinline__ void ldsm4(uint32_t* r, uint32_t a) {
    asm volatile("ldmatrix.sync.aligned.m8n8.x4.shared.b16 {%0,%1,%2,%3}, [%4];"
        : "=r"(r[0]), "=r"(r[1]), "=r"(r[2]), "=r"(r[3]) : "r"(a));
}
__device__ __forceinline__ void ldsm4t(uint32_t* r, uint32_t a) {
    asm volatile("ldmatrix.sync.aligned.m8n8.x4.trans.shared.b16 {%0,%1,%2,%3}, [%4];"
        : "=r"(r[0]), "=r"(r[1]), "=r"(r[2]), "=r"(r[3]) : "r"(a));
}
__device__ __forceinline__ void ldsm2t(uint32_t* r, uint32_t a) {
    asm volatile("ldmatrix.sync.aligned.m8n8.x2.trans.shared.b16 {%0,%1}, [%2];"
        : "=r"(r[0]), "=r"(r[1]) : "r"(a));
}
__device__ __forceinline__ uint32_t mulh2(uint32_t a, uint32_t b) {
    uint32_t d;
    asm("mul.rn.f16x2 %0, %1, %2;" : "=r"(d) : "r"(a), "r"(b));
    return d;
}
__device__ __forceinline__ void mma_f16(float* c, const uint32_t* a, const uint32_t* b) {
    asm volatile(
        "mma.sync.aligned.m16n8k16.row.col.f32.f16.f16.f32 "
        "{%0,%1,%2,%3}, {%4,%5,%6,%7}, {%8,%9}, {%0,%1,%2,%3};"
        : "+f"(c[0]), "+f"(c[1]), "+f"(c[2]), "+f"(c[3])
        : "r"(a[0]), "r"(a[1]), "r"(a[2]), "r"(a[3]), "r"(b[0]), "r"(b[1]));
}

// ---------------------------------------------------------------------------
// fp16 GEMM: C[M,N] = A[M,K] @ Bt[N,K]^T + bias[N]
// CTA 128x128, BK=64, 3-stage cp.async, 256 threads (8 warps, 2x4),
// warp tile 64x32. 2 CTAs/SM. (Byte-identical to R13/R14 — proven.)
// ---------------------------------------------------------------------------
#define BM 128
#define BN 128
#define BK 64
#define NST 3
#define SROWH 72
#define STAGE_H ((BM + BN) * SROWH)              // 18432 halves
#define GEMM_SMEM (NST * STAGE_H * 2)            // 110592 bytes
#define GTHREADS 256

template <bool HOUT>
__global__ __launch_bounds__(GTHREADS, 2) void gemm_h(
    const __half* __restrict__ A, const __half* __restrict__ Bt,
    const float* __restrict__ bias, void* __restrict__ Cv,
    int M, int N, int K)
{
    extern __shared__ __half smh[];
    const uint32_t sbase = smem_u32(smh);
    const int tid  = threadIdx.x;
    const int lane = tid & 31;
    const int w    = tid >> 5;
    const int wr   = w >> 2;
    const int wc   = w & 3;
    const int g    = lane >> 2;
    const int la3  = lane & 3;
    const int m4   = lane >> 3;
    const int ri   = lane & 7;
    const int row0 = blockIdx.y * BM;
    const int col0 = blockIdx.x * BN;

    float c[4][4][4];
    #pragma unroll
    for (int i = 0; i < 4; ++i)
        #pragma unroll
        for (int j = 0; j < 4; ++j)
            #pragma unroll
            for (int q = 0; q < 4; ++q) c[i][j][q] = 0.f;

    const int nchunk = K / BK;

    auto load_stage = [&](int s, int kt) {
        uint32_t sa = sbase + (uint32_t)(s * STAGE_H) * 2u;
        uint32_t sb = sa + (uint32_t)(BM * SROWH) * 2u;
        const __half* Ab = A  + (size_t)row0 * K + kt * BK;
        const __half* Bb = Bt + (size_t)col0 * K + kt * BK;
        #pragma unroll
        for (int it = 0; it < 4; ++it) {
            int idx = it * GTHREADS + tid;
            int r = idx >> 3, ch = (idx & 7) * 8;
            CP_ASYNC16(sa + (uint32_t)(r * SROWH + ch) * 2u, Ab + (size_t)r * K + ch);
        }
        #pragma unroll
        for (int it = 0; it < 4; ++it) {
            int idx = it * GTHREADS + tid;
            int r = idx >> 3, ch = (idx & 7) * 8;
            CP_ASYNC16(sb + (uint32_t)(r * SROWH + ch) * 2u, Bb + (size_t)r * K + ch);
        }
    };

    load_stage(0, 0); CP_COMMIT();
    load_stage(1, 1); CP_COMMIT();

    for (int kt = 0; kt < nchunk; ++kt) {
        CP_WAIT(1);
        __syncthreads();
        if (kt + 2 < nchunk) load_stage((kt + 2) % NST, kt + 2);
        CP_COMMIT();

        uint32_t sa = sbase + (uint32_t)((kt % NST) * STAGE_H) * 2u;
        uint32_t sb = sa + (uint32_t)(BM * SROWH) * 2u;
        #pragma unroll
        for (int ks = 0; ks < 4; ++ks) {
            uint32_t af[4][4], bf[4][2];
            #pragma unroll
            for (int mt = 0; mt < 4; ++mt) {
                int arow = wr * 64 + mt * 16 + (m4 & 1) * 8 + ri;
                int acol = ks * 16 + (m4 >> 1) * 8;
                ldsm4(af[mt], sa + (uint32_t)(arow * SROWH + acol) * 2u);
            }
            #pragma unroll
            for (int np = 0; np < 2; ++np) {
                int brow = wc * 32 + np * 16 + (m4 >> 1) * 8 + ri;
                int bcol = ks * 16 + (m4 & 1) * 8;
                uint32_t t[4];
                ldsm4(t, sb + (uint32_t)(brow * SROWH + bcol) * 2u);
                bf[np * 2][0] = t[0]; bf[np * 2][1] = t[1];
                bf[np * 2 + 1][0] = t[2]; bf[np * 2 + 1][1] = t[3];
            }
            #pragma unroll
            for (int mt = 0; mt < 4; ++mt)
                #pragma unroll
                for (int nt = 0; nt < 4; ++nt)
                    mma_f16(c[mt][nt], af[mt], bf[nt]);
        }
    }

    #pragma unroll
    for (int mt = 0; mt < 4; ++mt) {
        #pragma unroll
        for (int nt = 0; nt < 4; ++nt) {
            int r   = row0 + wr * 64 + mt * 16 + g;
            int col = col0 + wc * 32 + nt * 8 + la3 * 2;
            float2 bv = *(const float2*)&bias[col];
            float v00 = c[mt][nt][0] + bv.x, v01 = c[mt][nt][1] + bv.y;
            float v10 = c[mt][nt][2] + bv.x, v11 = c[mt][nt][3] + bv.y;
            if (HOUT) {
                __half* C = (__half*)Cv;
                *(__half2*)&C[(size_t)r * N + col]       = __floats2half2_rn(v00, v01);
                *(__half2*)&C[(size_t)(r + 8) * N + col] = __floats2half2_rn(v10, v11);
            } else {
                float* C = (float*)Cv;
                *(float2*)&C[(size_t)r * N + col]       = make_float2(v00, v01);
                *(float2*)&C[(size_t)(r + 8) * N + col] = make_float2(v10, v11);
            }
        }
    }
}

// ---------------------------------------------------------------------------
// Fused prep: one launch. Regions by blockIdx.x:
//   [0, 4096):        cvt x f32->f16            (4 elems/thread)
//   [4096, 7168):     transpose+cvt W_qkv
//   [7168, 8192):     transpose+cvt W_o
// ---------------------------------------------------------------------------
__global__ __launch_bounds__(256) void prep_all(
    const float* __restrict__ x, const float* __restrict__ wq,
    const float* __restrict__ wo,
    __half* __restrict__ xh, __half* __restrict__ wqt, __half* __restrict__ wot)
{
    const int bid = blockIdx.x;
    const int tid = threadIdx.x;
    if (bid < 4096) {
        int i = (bid * 256 + tid) * 4;
        float4 v = *(const float4*)&x[i];
        *(__half2*)&xh[i]     = __floats2half2_rn(v.x, v.y);
        *(__half2*)&xh[i + 2] = __floats2half2_rn(v.z, v.w);
        return;
    }
    __shared__ float t[32][33];
    const float* in; __half* out; int R, Ccols, bx, by;
    if (bid < 7168) {
        int lb = bid - 4096; bx = lb % 96; by = lb / 96;
        in = wq; out = wqt; R = CDIM; Ccols = QKV_N;
    } else {
        int lb = bid - 7168; bx = lb & 31; by = lb >> 5;
        in = wo; out = wot; R = CDIM; Ccols = CDIM;
    }
    int tx = tid & 31, ty = tid >> 5;
    int r0 = by * 32, c0 = bx * 32;
    #pragma unroll
    for (int i = ty; i < 32; i += 8)
        t[i][tx] = in[(size_t)(r0 + i) * Ccols + c0 + tx];
    __syncthreads();
    #pragma unroll
    for (int i = ty; i < 32; i += 8)
        out[(size_t)(c0 + i) * R + r0 + tx] = __float2half_rn(t[tx][i]);
}

// ---------------------------------------------------------------------------
// Flash attention (causal), fp16 mma + ldmatrix. R14 design plus:
//  * BALLOT-GUARDED RESCALE: the corr-rescale (2 expf + 40 FMUL) executes
//    only when some lane's running max actually increased. When skipped,
//    corr == 1 exactly -> bit-identical results. Max stabilizes after the
//    first few tiles (P[new tile max > running max] ~ 1/t), so the guard
//    removes nearly all rescale work.
// ---------------------------------------------------------------------------
#define AQ 128
#define AKV 64
#define NSTG 4
#define ASTRH 72
#define SMQ_H 0
#define SMK_H (AQ * ASTRH)                        // 9216
#define SMV_H (SMK_H + NSTG * AKV * ASTRH)        // 27648
#define ATTN_SMEM ((SMV_H + NSTG * AKV * ASTRH) * 2)  // 92160 bytes

__global__ __launch_bounds__(256, 2) void attn_h(
    const __half* __restrict__ qkv, __half* __restrict__ y)
{
    extern __shared__ __half smh[];
    const uint32_t sb = smem_u32(smh);
    const int tid  = threadIdx.x;
    const int lane = tid & 31;
    const int w    = tid >> 5;
    const int g    = lane >> 2;
    const int la3  = lane & 3;
    const int m4   = lane >> 3;
    const int ri   = lane & 7;

    const int qblk = (gridDim.x - 1) - blockIdx.x;   // heavy blocks first
    const int q0   = qblk * AQ;
    const int h    = blockIdx.y;
    const int b    = blockIdx.z;
    const size_t base = (size_t)b * TSEQ * QKV_N + h * HDIM;

    auto load_kv = [&](int t, int stage) {
        uint32_t ks_ = sb + (uint32_t)(SMK_H + stage * AKV * ASTRH) * 2u;
        uint32_t vs_ = sb + (uint32_t)(SMV_H + stage * AKV * ASTRH) * 2u;
        const __half* Kg = qkv + base + CDIM     + (size_t)t * AKV * QKV_N;
        const __half* Vg = qkv + base + 2 * CDIM + (size_t)t * AKV * QKV_N;
        #pragma unroll
        for (int it = 0; it < 2; ++it) {
            int idx = it * 256 + tid;
            int r = idx >> 3, ch = (idx & 7) * 8;
            CP_ASYNC16(ks_ + (uint32_t)(r * ASTRH + ch) * 2u, Kg + (size_t)r * QKV_N + ch);
            CP_ASYNC16(vs_ + (uint32_t)(r * ASTRH + ch) * 2u, Vg + (size_t)r * QKV_N + ch);
        }
    };

    const int ntile = q0 / AKV + 2;

    // Ones padding for all V stages (cols 64-71); cp.async never writes them.
    {
        const uint32_t ONE2 = 0x3C003C00u;
        for (int r = tid; r < NSTG * AKV; r += 256) {
            uint4 v = make_uint4(ONE2, ONE2, ONE2, ONE2);
            *(uint4*)&smh[SMV_H + r * ASTRH + 64] = v;
        }
    }

    // Prologue: group [Q], then groups [T0], [T1], [T2]
    #pragma unroll
    for (int it = 0; it < 4; ++it) {
        int idx = it * 256 + tid;
        int r = idx >> 3, ch = (idx & 7) * 8;
        CP_ASYNC16(sb + (uint32_t)(SMQ_H + r * ASTRH + ch) * 2u,
                   qkv + base + (size_t)(q0 + r) * QKV_N + ch);
    }
    CP_COMMIT();
    load_kv(0, 0); CP_COMMIT();
    if (1 < ntile) load_kv(1, 1);
    CP_COMMIT();
    if (2 < ntile) load_kv(2, 2);
    CP_COMMIT();
    CP_WAIT(3);
    __syncthreads();   // publishes Q + ones padding

    // Q fragments, pre-scaled by 1/8 (exact exponent shift in fp16)
    uint32_t qf[4][4];
    const uint32_t SC = 0x30003000u;   // half2(0.125, 0.125)
    #pragma unroll
    for (int ks = 0; ks < 4; ++ks) {
        int qrow = w * 16 + (m4 & 1) * 8 + ri;
        int qcol = ks * 16 + (m4 >> 1) * 8;
        ldsm4(qf[ks], sb + (uint32_t)(SMQ_H + qrow * ASTRH + qcol) * 2u);
        #pragma unroll
        for (int i = 0; i < 4; ++i) qf[ks][i] = mulh2(qf[ks][i], SC);
    }

    float o[8][4];
    #pragma unroll
    for (int nt = 0; nt < 8; ++nt)
        #pragma unroll
        for (int q = 0; q < 4; ++q) o[nt][q] = 0.f;
    float o_l[4] = {0.f, 0.f, 0.f, 0.f};       // l-sums via ones column
    float m0 = -1e30f, m1 = -1e30f;

    const int row1 = q0 + w * 16 + g;
    const int row2 = row1 + 8;

    for (int t = 0; t < ntile; ++t) {
        CP_WAIT(2);
        __syncthreads();
        if (t + 3 < ntile) load_kv(t + 3, (t + 3) & (NSTG - 1));
        CP_COMMIT();

        const int st = t & (NSTG - 1);
        const uint32_t ksb = sb + (uint32_t)(SMK_H + st * AKV * ASTRH) * 2u;
        const uint32_t vsb = sb + (uint32_t)(SMV_H + st * AKV * ASTRH) * 2u;

        // S = (Q/8) K^T
        float s[8][4];
        #pragma unroll
        for (int nt = 0; nt < 8; ++nt)
            #pragma unroll
            for (int q = 0; q < 4; ++q) s[nt][q] = 0.f;
        #pragma unroll
        for (int ks = 0; ks < 4; ++ks) {
            #pragma unroll
            for (int np = 0; np < 4; ++np) {
                int krow = np * 16 + (m4 >> 1) * 8 + ri;
                int kcol = ks * 16 + (m4 & 1) * 8;
                uint32_t tr[4];
                ldsm4(tr, ksb + (uint32_t)(krow * ASTRH + kcol) * 2u);
                uint32_t b0[2] = { tr[0], tr[1] };
                uint32_t b1[2] = { tr[2], tr[3] };
                mma_f16(s[np * 2],     qf[ks], b0);
                mma_f16(s[np * 2 + 1], qf[ks], b1);
            }
        }

        // causal mask
        const int j0 = t * AKV;
        if (j0 >= q0) {
            #pragma unroll
            for (int nt = 0; nt < 8; ++nt) {
                int col = j0 + nt * 8 + 2 * la3;
                if (col     > row1) s[nt][0] = -1e30f;
                if (col + 1 > row1) s[nt][1] = -1e30f;
                if (col     > row2) s[nt][2] = -1e30f;
                if (col + 1 > row2) s[nt][3] = -1e30f;
            }
        }

        // row max
        float mx0 = -1e30f, mx1 = -1e30f;
        #pragma unroll
        for (int nt = 0; nt < 8; ++nt) {
            mx0 = fmaxf(mx0, fmaxf(s[nt][0], s[nt][1]));
            mx1 = fmaxf(mx1, fmaxf(s[nt][2], s[nt][3]));
        }
        mx0 = fmaxf(mx0, __shfl_xor_sync(0xffffffffu, mx0, 1));
        mx0 = fmaxf(mx0, __shfl_xor_sync(0xffffffffu, mx0, 2));
        mx1 = fmaxf(mx1, __shfl_xor_sync(0xffffffffu, mx1, 1));
        mx1 = fmaxf(mx1, __shfl_xor_sync(0xffffffffu, mx1, 2));

        float M0 = fmaxf(m0, mx0), M1 = fmaxf(m1, mx1);

        // Ballot-guarded rescale: skipped warp-uniformly when no lane's max
        // increased (then corr == 1 exactly -> bit-identical to executing).
        bool upd = (M0 > m0) || (M1 > m1);
        if (__ballot_sync(0xffffffffu, upd)) {
            float corr0 = __expf(m0 - M0), corr1 = __expf(m1 - M1);
            #pragma unroll
            for (int nt = 0; nt < 8; ++nt) {
                o[nt][0] *= corr0; o[nt][1] *= corr0;
                o[nt][2] *= corr1; o[nt][3] *= corr1;
            }
            o_l[0] *= corr0; o_l[1] *= corr0;
            o_l[2] *= corr1; o_l[3] *= corr1;
        }
        m0 = M0; m1 = M1;

        // P = exp(S - M) packed to fp16 A-frags
        uint32_t pf[4][4];
        #pragma unroll
        for (int j = 0; j < 4; ++j) {
            __half2 h00 = __floats2half2_rn(__expf(s[2*j][0]   - M0), __expf(s[2*j][1]   - M0));
            __half2 h01 = __floats2half2_rn(__expf(s[2*j][2]   - M1), __expf(s[2*j][3]   - M1));
            __half2 h10 = __floats2half2_rn(__expf(s[2*j+1][0] - M0), __expf(s[2*j+1][1] - M0));
            __half2 h11 = __floats2half2_rn(__expf(s[2*j+1][2] - M1), __expf(s[2*j+1][3] - M1));
            pf[j][0] = *(uint32_t*)&h00;
            pf[j][1] = *(uint32_t*)&h01;
            pf[j][2] = *(uint32_t*)&h10;
            pf[j][3] = *(uint32_t*)&h11;
        }

        // O += P V ; o_l += P * ones (rowsum, shuffle-free)
        #pragma unroll
        for (int j = 0; j < 4; ++j) {
            uint32_t tro[2];
            ldsm2t(tro, vsb + (uint32_t)((j * 16 + (lane & 15)) * ASTRH + 64) * 2u);
            mma_f16(o_l, pf[j], tro);
            #pragma unroll
            for (int np = 0; np < 4; ++np) {
                int vrow = j * 16 + (m4 & 1) * 8 + ri;
                int vcol = np * 16 + (m4 >> 1) * 8;
                uint32_t tr[4];
                ldsm4t(tr, vsb + (uint32_t)(vrow * ASTRH + vcol) * 2u);
                uint32_t b0[2] = { tr[0], tr[1] };
                uint32_t b1[2] = { tr[2], tr[3] };
                mma_f16(o[np * 2],     pf[j], b0);
                mma_f16(o[np * 2 + 1], pf[j], b1);
            }
        }
    }

    const float inv0 = 1.f / o_l[0], inv1 = 1.f / o_l[2];
    __half* y1 = &y[((size_t)b * TSEQ + row1) * CDIM + h * HDIM];
    __half* y2 = &y[((size_t)b * TSEQ + row2) * CDIM + h * HDIM];
    #pragma unroll
    for (int nt = 0; nt < 8; ++nt) {
        int col = nt * 8 + 2 * la3;
        *(__half2*)&y1[col] = __floats2half2_rn(o[nt][0] * inv0, o[nt][1] * inv0);
        *(__half2*)&y2[col] = __floats2half2_rn(o[nt][2] * inv1, o[nt][3] * inv1);
    }
}

// ---------------------------------------------------------------------------
extern "C" void kernel_launch(void* const* d_in, const int* in_sizes, int n_in,
                              void* d_out, int out_size)
{
    const float* x     = (const float*)d_in[0];
    const float* W_qkv = (const float*)d_in[1];
    const float* b_qkv = (const float*)d_in[2];
    const float* W_o   = (const float*)d_in[3];
    const float* b_o   = (const float*)d_in[4];
    float* out = (float*)d_out;

    __half *qkv_ptr, *yh_ptr, *xh_ptr, *wtq_ptr, *wto_ptr;
    cudaGetSymbolAddress((void**)&qkv_ptr, g_qkvh);
    cudaGetSymbolAddress((void**)&yh_ptr,  g_yh);
    cudaGetSymbolAddress((void**)&xh_ptr,  g_xh);
    cudaGetSymbolAddress((void**)&wtq_ptr, g_wtq);
    cudaGetSymbolAddress((void**)&wto_ptr, g_wto);

    cudaFuncSetAttribute(gemm_h<true>,  cudaFuncAttributeMaxDynamicSharedMemorySize, GEMM_SMEM);
    cudaFuncSetAttribute(gemm_h<false>, cudaFuncAttributeMaxDynamicSharedMemorySize, GEMM_SMEM);
    cudaFuncSetAttribute(attn_h, cudaFuncAttributeMaxDynamicSharedMemorySize, ATTN_SMEM);

    // Fused prep: convert x + transpose/convert both weight matrices
    prep_all<<<8192, 256>>>(x, W_qkv, W_o, xh_ptr, wtq_ptr, wto_ptr);

    // qkv = half(x @ W_qkv + b_qkv)   [4096, 3072]
    gemm_h<true><<<dim3(QKV_N / BN, MROWS / BM), GTHREADS, GEMM_SMEM>>>(
        xh_ptr, wtq_ptr, b_qkv, qkv_ptr, MROWS, QKV_N, CDIM);

    // y = attention(qkv)  (half out)
    attn_h<<<dim3(TSEQ / AQ, NHEAD, BATCH), 256, ATTN_SMEM>>>(qkv_ptr, yh_ptr);

    // out = y @ W_o + b_o   [4096, 1024] fp32 out
    gemm_h<false><<<dim3(CDIM / BN, MROWS / BM), GTHREADS, GEMM_SMEM>>>(
        yh_ptr, wto_ptr, b_o, out, MROWS, CDIM, CDIM);
}

// round 17
// speedup vs baseline: 1.0358x; 1.0358x over previous
#include <cuda_runtime.h>
#include <cuda_fp16.h>
#include <math.h>
#include <cstdint>

#define BATCH 2
#define TSEQ  2048
#define CDIM  1024
#define NHEAD 16
#define HDIM  64
#define MROWS (BATCH*TSEQ)          // 4096
#define QKV_N (3*CDIM)              // 3072

// Scratch (no runtime allocation allowed)
__device__ __half g_qkvh[MROWS * QKV_N];    // [B*T, 3C] half
__device__ __half g_yh  [MROWS * CDIM];     // [B*T, C]  half (attn out)
__device__ __half g_xh  [MROWS * CDIM];     // half copy of x
__device__ __half g_wtq [QKV_N * CDIM];     // W_qkv^T half
__device__ __half g_wto [CDIM * CDIM];      // W_o^T   half

// ---------------------------------------------------------------------------
// helpers
// ---------------------------------------------------------------------------
__device__ __forceinline__ uint32_t smem_u32(const void* p) {
    uint32_t a;
    asm("{ .reg .u64 t; cvta.to.shared.u64 t, %1; cvt.u32.u64 %0, t; }" : "=r"(a) : "l"(p));
    return a;
}
#define CP_ASYNC16(dst, src) \
    asm volatile("cp.async.cg.shared.global [%0], [%1], 16;" :: "r"(dst), "l"(src) : "memory")
#define CP_COMMIT() asm volatile("cp.async.commit_group;" ::: "memory")
#define CP_WAIT(n)  asm volatile("cp.async.wait_group %0;" :: "n"(n) : "memory")

__device__ __forceinline__ void ldsm4(uint32_t* r, uint32_t a) {
    asm volatile("ldmatrix.sync.aligned.m8n8.x4.shared.b16 {%0,%1,%2,%3}, [%4];"
        : "=r"(r[0]), "=r"(r[1]), "=r"(r[2]), "=r"(r[3]) : "r"(a));
}
__device__ __forceinline__ void ldsm4t(uint32_t* r, uint32_t a) {
    asm volatile("ldmatrix.sync.aligned.m8n8.x4.trans.shared.b16 {%0,%1,%2,%3}, [%4];"
        : "=r"(r[0]), "=r"(r[1]), "=r"(r[2]), "=r"(r[3]) : "r"(a));
}
__device__ __forceinline__ void ldsm2t(uint32_t* r, uint32_t a) {
    asm volatile("ldmatrix.sync.aligned.m8n8.x2.trans.shared.b16 {%0,%1}, [%2];"
        : "=r"(r[0]), "=r"(r[1]) : "r"(a));
}
__device__ __forceinline__ uint32_t mulh2(uint32_t a, uint32_t b) {
    uint32_t d;
    asm("mul.rn.f16x2 %0, %1, %2;" : "=r"(d) : "r"(a), "r"(b));
    return d;
}
__device__ __forceinline__ float ex2(float x) {
    float r;
    asm("ex2.approx.ftz.f32 %0, %1;" : "=f"(r) : "f"(x));
    return r;
}
__device__ __forceinline__ void mma_f16(float* c, const uint32_t* a, const uint32_t* b) {
    asm volatile(
        "mma.sync.aligned.m16n8k16.row.col.f32.f16.f16.f32 "
        "{%0,%1,%2,%3}, {%4,%5,%6,%7}, {%8,%9}, {%0,%1,%2,%3};"
        : "+f"(c[0]), "+f"(c[1]), "+f"(c[2]), "+f"(c[3])
        : "r"(a[0]), "r"(a[1]), "r"(a[2]), "r"(a[3]), "r"(b[0]), "r"(b[1]));
}

// ---------------------------------------------------------------------------
// fp16 GEMM: C[M,N] = A[M,K] @ Bt[N,K]^T + bias[N]
// CTA 128x128, BK=64, 3-stage cp.async, 256 threads (8 warps, 2x4),
// warp tile 64x32. 2 CTAs/SM. (Byte-identical to R13/R14/R15 — proven.)
// ---------------------------------------------------------------------------
#define BM 128
#define BN 128
#define BK 64
#define NST 3
#define SROWH 72
#define STAGE_H ((BM + BN) * SROWH)              // 18432 halves
#define GEMM_SMEM (NST * STAGE_H * 2)            // 110592 bytes
#define GTHREADS 256

template <bool HOUT>
__global__ __launch_bounds__(GTHREADS, 2) void gemm_h(
    const __half* __restrict__ A, const __half* __restrict__ Bt,
    const float* __restrict__ bias, void* __restrict__ Cv,
    int M, int N, int K)
{
    extern __shared__ __half smh[];
    const uint32_t sbase = smem_u32(smh);
    const int tid  = threadIdx.x;
    const int lane = tid & 31;
    const int w    = tid >> 5;
    const int wr   = w >> 2;
    const int wc   = w & 3;
    const int g    = lane >> 2;
    const int la3  = lane & 3;
    const int m4   = lane >> 3;
    const int ri   = lane & 7;
    const int row0 = blockIdx.y * BM;
    const int col0 = blockIdx.x * BN;

    float c[4][4][4];
    #pragma unroll
    for (int i = 0; i < 4; ++i)
        #pragma unroll
        for (int j = 0; j < 4; ++j)
            #pragma unroll
            for (int q = 0; q < 4; ++q) c[i][j][q] = 0.f;

    const int nchunk = K / BK;

    auto load_stage = [&](int s, int kt) {
        uint32_t sa = sbase + (uint32_t)(s * STAGE_H) * 2u;
        uint32_t sb = sa + (uint32_t)(BM * SROWH) * 2u;
        const __half* Ab = A  + (size_t)row0 * K + kt * BK;
        const __half* Bb = Bt + (size_t)col0 * K + kt * BK;
        #pragma unroll
        for (int it = 0; it < 4; ++it) {
            int idx = it * GTHREADS + tid;
            int r = idx >> 3, ch = (idx & 7) * 8;
            CP_ASYNC16(sa + (uint32_t)(r * SROWH + ch) * 2u, Ab + (size_t)r * K + ch);
        }
        #pragma unroll
        for (int it = 0; it < 4; ++it) {
            int idx = it * GTHREADS + tid;
            int r = idx >> 3, ch = (idx & 7) * 8;
            CP_ASYNC16(sb + (uint32_t)(r * SROWH + ch) * 2u, Bb + (size_t)r * K + ch);
        }
    };

    load_stage(0, 0); CP_COMMIT();
    load_stage(1, 1); CP_COMMIT();

    for (int kt = 0; kt < nchunk; ++kt) {
        CP_WAIT(1);
        __syncthreads();
        if (kt + 2 < nchunk) load_stage((kt + 2) % NST, kt + 2);
        CP_COMMIT();

        uint32_t sa = sbase + (uint32_t)((kt % NST) * STAGE_H) * 2u;
        uint32_t sb = sa + (uint32_t)(BM * SROWH) * 2u;
        #pragma unroll
        for (int ks = 0; ks < 4; ++ks) {
            uint32_t af[4][4], bf[4][2];
            #pragma unroll
            for (int mt = 0; mt < 4; ++mt) {
                int arow = wr * 64 + mt * 16 + (m4 & 1) * 8 + ri;
                int acol = ks * 16 + (m4 >> 1) * 8;
                ldsm4(af[mt], sa + (uint32_t)(arow * SROWH + acol) * 2u);
            }
            #pragma unroll
            for (int np = 0; np < 2; ++np) {
                int brow = wc * 32 + np * 16 + (m4 >> 1) * 8 + ri;
                int bcol = ks * 16 + (m4 & 1) * 8;
                uint32_t t[4];
                ldsm4(t, sb + (uint32_t)(brow * SROWH + bcol) * 2u);
                bf[np * 2][0] = t[0]; bf[np * 2][1] = t[1];
                bf[np * 2 + 1][0] = t[2]; bf[np * 2 + 1][1] = t[3];
            }
            #pragma unroll
            for (int mt = 0; mt < 4; ++mt)
                #pragma unroll
                for (int nt = 0; nt < 4; ++nt)
                    mma_f16(c[mt][nt], af[mt], bf[nt]);
        }
    }

    #pragma unroll
    for (int mt = 0; mt < 4; ++mt) {
        #pragma unroll
        for (int nt = 0; nt < 4; ++nt) {
            int r   = row0 + wr * 64 + mt * 16 + g;
            int col = col0 + wc * 32 + nt * 8 + la3 * 2;
            float2 bv = *(const float2*)&bias[col];
            float v00 = c[mt][nt][0] + bv.x, v01 = c[mt][nt][1] + bv.y;
            float v10 = c[mt][nt][2] + bv.x, v11 = c[mt][nt][3] + bv.y;
            if (HOUT) {
                __half* C = (__half*)Cv;
                *(__half2*)&C[(size_t)r * N + col]       = __floats2half2_rn(v00, v01);
                *(__half2*)&C[(size_t)(r + 8) * N + col] = __floats2half2_rn(v10, v11);
            } else {
                float* C = (float*)Cv;
                *(float2*)&C[(size_t)r * N + col]       = make_float2(v00, v01);
                *(float2*)&C[(size_t)(r + 8) * N + col] = make_float2(v10, v11);
            }
        }
    }
}

// ---------------------------------------------------------------------------
// Fused prep: one launch. Regions by blockIdx.x:
//   [0, 4096):        cvt x f32->f16            (4 elems/thread)
//   [4096, 7168):     transpose+cvt W_qkv
//   [7168, 8192):     transpose+cvt W_o
// ---------------------------------------------------------------------------
__global__ __launch_bounds__(256) void prep_all(
    const float* __restrict__ x, const float* __restrict__ wq,
    const float* __restrict__ wo,
    __half* __restrict__ xh, __half* __restrict__ wqt, __half* __restrict__ wot)
{
    const int bid = blockIdx.x;
    const int tid = threadIdx.x;
    if (bid < 4096) {
        int i = (bid * 256 + tid) * 4;
        float4 v = *(const float4*)&x[i];
        *(__half2*)&xh[i]     = __floats2half2_rn(v.x, v.y);
        *(__half2*)&xh[i + 2] = __floats2half2_rn(v.z, v.w);
        return;
    }
    __shared__ float t[32][33];
    const float* in; __half* out; int R, Ccols, bx, by;
    if (bid < 7168) {
        int lb = bid - 4096; bx = lb % 96; by = lb / 96;
        in = wq; out = wqt; R = CDIM; Ccols = QKV_N;
    } else {
        int lb = bid - 7168; bx = lb & 31; by = lb >> 5;
        in = wo; out = wot; R = CDIM; Ccols = CDIM;
    }
    int tx = tid & 31, ty = tid >> 5;
    int r0 = by * 32, c0 = bx * 32;
    #pragma unroll
    for (int i = ty; i < 32; i += 8)
        t[i][tx] = in[(size_t)(r0 + i) * Ccols + c0 + tx];
    __syncthreads();
    #pragma unroll
    for (int i = ty; i < 32; i += 8)
        out[(size_t)(c0 + i) * R + r0 + tx] = __float2half_rn(t[tx][i]);
}

// ---------------------------------------------------------------------------
// Flash attention (causal), fp16 mma + ldmatrix. R15 design plus BASE-2
// SOFTMAX: log2(e) folded into the Q scale (log2e/8 in fp16), so S is in
// log2 domain and every exp becomes a bare ex2.approx (one MUFU, no FMUL).
// Deletes 18 FMULs/thread/tile and shortens the exp dependency chain.
// ---------------------------------------------------------------------------
#define AQ 128
#define AKV 64
#define NSTG 4
#define ASTRH 72
#define SMQ_H 0
#define SMK_H (AQ * ASTRH)                        // 9216
#define SMV_H (SMK_H + NSTG * AKV * ASTRH)        // 27648
#define ATTN_SMEM ((SMV_H + NSTG * AKV * ASTRH) * 2)  // 92160 bytes

__global__ __launch_bounds__(256, 2) void attn_h(
    const __half* __restrict__ qkv, __half* __restrict__ y)
{
    extern __shared__ __half smh[];
    const uint32_t sb = smem_u32(smh);
    const int tid  = threadIdx.x;
    const int lane = tid & 31;
    const int w    = tid >> 5;
    const int g    = lane >> 2;
    const int la3  = lane & 3;
    const int m4   = lane >> 3;
    const int ri   = lane & 7;

    const int qblk = (gridDim.x - 1) - blockIdx.x;   // heavy blocks first
    const int q0   = qblk * AQ;
    const int h    = blockIdx.y;
    const int b    = blockIdx.z;
    const size_t base = (size_t)b * TSEQ * QKV_N + h * HDIM;

    auto load_kv = [&](int t, int stage) {
        uint32_t ks_ = sb + (uint32_t)(SMK_H + stage * AKV * ASTRH) * 2u;
        uint32_t vs_ = sb + (uint32_t)(SMV_H + stage * AKV * ASTRH) * 2u;
        const __half* Kg = qkv + base + CDIM     + (size_t)t * AKV * QKV_N;
        const __half* Vg = qkv + base + 2 * CDIM + (size_t)t * AKV * QKV_N;
        #pragma unroll
        for (int it = 0; it < 2; ++it) {
            int idx = it * 256 + tid;
            int r = idx >> 3, ch = (idx & 7) * 8;
            CP_ASYNC16(ks_ + (uint32_t)(r * ASTRH + ch) * 2u, Kg + (size_t)r * QKV_N + ch);
            CP_ASYNC16(vs_ + (uint32_t)(r * ASTRH + ch) * 2u, Vg + (size_t)r * QKV_N + ch);
        }
    };

    const int ntile = q0 / AKV + 2;

    // Ones padding for all V stages (cols 64-71); cp.async never writes them.
    {
        const uint32_t ONE2 = 0x3C003C00u;
        for (int r = tid; r < NSTG * AKV; r += 256) {
            uint4 v = make_uint4(ONE2, ONE2, ONE2, ONE2);
            *(uint4*)&smh[SMV_H + r * ASTRH + 64] = v;
        }
    }

    // Prologue: group [Q], then groups [T0], [T1], [T2]
    #pragma unroll
    for (int it = 0; it < 4; ++it) {
        int idx = it * 256 + tid;
        int r = idx >> 3, ch = (idx & 7) * 8;
        CP_ASYNC16(sb + (uint32_t)(SMQ_H + r * ASTRH + ch) * 2u,
                   qkv + base + (size_t)(q0 + r) * QKV_N + ch);
    }
    CP_COMMIT();
    load_kv(0, 0); CP_COMMIT();
    if (1 < ntile) load_kv(1, 1);
    CP_COMMIT();
    if (2 < ntile) load_kv(2, 2);
    CP_COMMIT();
    CP_WAIT(3);
    __syncthreads();   // publishes Q + ones padding

    // Q fragments, pre-scaled by log2(e)/8 (base-2 softmax domain)
    uint32_t qf[4][4];
    const __half2 sch = __floats2half2_rn(0.1803368867f, 0.1803368867f);
    const uint32_t SC = *(const uint32_t*)&sch;
    #pragma unroll
    for (int ks = 0; ks < 4; ++ks) {
        int qrow = w * 16 + (m4 & 1) * 8 + ri;
        int qcol = ks * 16 + (m4 >> 1) * 8;
        ldsm4(qf[ks], sb + (uint32_t)(SMQ_H + qrow * ASTRH + qcol) * 2u);
        #pragma unroll
        for (int i = 0; i < 4; ++i) qf[ks][i] = mulh2(qf[ks][i], SC);
    }

    float o[8][4];
    #pragma unroll
    for (int nt = 0; nt < 8; ++nt)
        #pragma unroll
        for (int q = 0; q < 4; ++q) o[nt][q] = 0.f;
    float o_l[4] = {0.f, 0.f, 0.f, 0.f};       // l-sums via ones column
    float m0 = -1e30f, m1 = -1e30f;

    const int row1 = q0 + w * 16 + g;
    const int row2 = row1 + 8;

    for (int t = 0; t < ntile; ++t) {
        CP_WAIT(2);
        __syncthreads();
        if (t + 3 < ntile) load_kv(t + 3, (t + 3) & (NSTG - 1));
        CP_COMMIT();

        const int st = t & (NSTG - 1);
        const uint32_t ksb = sb + (uint32_t)(SMK_H + st * AKV * ASTRH) * 2u;
        const uint32_t vsb = sb + (uint32_t)(SMV_H + st * AKV * ASTRH) * 2u;

        // S = (Q * log2e/8) K^T   (log2 domain)
        float s[8][4];
        #pragma unroll
        for (int nt = 0; nt < 8; ++nt)
            #pragma unroll
            for (int q = 0; q < 4; ++q) s[nt][q] = 0.f;
        #pragma unroll
        for (int ks = 0; ks < 4; ++ks) {
            #pragma unroll
            for (int np = 0; np < 4; ++np) {
                int krow = np * 16 + (m4 >> 1) * 8 + ri;
                int kcol = ks * 16 + (m4 & 1) * 8;
                uint32_t tr[4];
                ldsm4(tr, ksb + (uint32_t)(krow * ASTRH + kcol) * 2u);
                uint32_t b0[2] = { tr[0], tr[1] };
                uint32_t b1[2] = { tr[2], tr[3] };
                mma_f16(s[np * 2],     qf[ks], b0);
                mma_f16(s[np * 2 + 1], qf[ks], b1);
            }
        }

        // causal mask
        const int j0 = t * AKV;
        if (j0 >= q0) {
            #pragma unroll
            for (int nt = 0; nt < 8; ++nt) {
                int col = j0 + nt * 8 + 2 * la3;
                if (col     > row1) s[nt][0] = -1e30f;
                if (col + 1 > row1) s[nt][1] = -1e30f;
                if (col     > row2) s[nt][2] = -1e30f;
                if (col + 1 > row2) s[nt][3] = -1e30f;
            }
        }

        // row max
        float mx0 = -1e30f, mx1 = -1e30f;
        #pragma unroll
        for (int nt = 0; nt < 8; ++nt) {
            mx0 = fmaxf(mx0, fmaxf(s[nt][0], s[nt][1]));
            mx1 = fmaxf(mx1, fmaxf(s[nt][2], s[nt][3]));
        }
        mx0 = fmaxf(mx0, __shfl_xor_sync(0xffffffffu, mx0, 1));
        mx0 = fmaxf(mx0, __shfl_xor_sync(0xffffffffu, mx0, 2));
        mx1 = fmaxf(mx1, __shfl_xor_sync(0xffffffffu, mx1, 1));
        mx1 = fmaxf(mx1, __shfl_xor_sync(0xffffffffu, mx1, 2));

        float M0 = fmaxf(m0, mx0), M1 = fmaxf(m1, mx1);

        // Ballot-guarded rescale (corr == 1 when skipped -> bit-identical)
        bool upd = (M0 > m0) || (M1 > m1);
        if (__ballot_sync(0xffffffffu, upd)) {
            float corr0 = ex2(m0 - M0), corr1 = ex2(m1 - M1);
            #pragma unroll
            for (int nt = 0; nt < 8; ++nt) {
                o[nt][0] *= corr0; o[nt][1] *= corr0;
                o[nt][2] *= corr1; o[nt][3] *= corr1;
            }
            o_l[0] *= corr0; o_l[1] *= corr0;
            o_l[2] *= corr1; o_l[3] *= corr1;
        }
        m0 = M0; m1 = M1;

        // P = 2^(S - M) packed to fp16 A-frags (bare MUFU.EX2, no FMUL)
        uint32_t pf[4][4];
        #pragma unroll
        for (int j = 0; j < 4; ++j) {
            __half2 h00 = __floats2half2_rn(ex2(s[2*j][0]   - M0), ex2(s[2*j][1]   - M0));
            __half2 h01 = __floats2half2_rn(ex2(s[2*j][2]   - M1), ex2(s[2*j][3]   - M1));
            __half2 h10 = __floats2half2_rn(ex2(s[2*j+1][0] - M0), ex2(s[2*j+1][1] - M0));
            __half2 h11 = __floats2half2_rn(ex2(s[2*j+1][2] - M1), ex2(s[2*j+1][3] - M1));
            pf[j][0] = *(uint32_t*)&h00;
            pf[j][1] = *(uint32_t*)&h01;
            pf[j][2] = *(uint32_t*)&h10;
            pf[j][3] = *(uint32_t*)&h11;
        }

        // O += P V ; o_l += P * ones (rowsum, shuffle-free)
        #pragma unroll
        for (int j = 0; j < 4; ++j) {
            uint32_t tro[2];
            ldsm2t(tro, vsb + (uint32_t)((j * 16 + (lane & 15)) * ASTRH + 64) * 2u);
            mma_f16(o_l, pf[j], tro);
            #pragma unroll
            for (int np = 0; np < 4; ++np) {
                int vrow = j * 16 + (m4 & 1) * 8 + ri;
                int vcol = np * 16 + (m4 >> 1) * 8;
                uint32_t tr[4];
                ldsm4t(tr, vsb + (uint32_t)(vrow * ASTRH + vcol) * 2u);
                uint32_t b0[2] = { tr[0], tr[1] };
                uint32_t b1[2] = { tr[2], tr[3] };
                mma_f16(o[np * 2],     pf[j], b0);
                mma_f16(o[np * 2 + 1], pf[j], b1);
            }
        }
    }

    const float inv0 = 1.f / o_l[0], inv1 = 1.f / o_l[2];
    __half* y1 = &y[((size_t)b * TSEQ + row1) * CDIM + h * HDIM];
    __half* y2 = &y[((size_t)b * TSEQ + row2) * CDIM + h * HDIM];
    #pragma unroll
    for (int nt = 0; nt < 8; ++nt) {
        int col = nt * 8 + 2 * la3;
        *(__half2*)&y1[col] = __floats2half2_rn(o[nt][0] * inv0, o[nt][1] * inv0);
        *(__half2*)&y2[col] = __floats2half2_rn(o[nt][2] * inv1, o[nt][3] * inv1);
    }
}

// ---------------------------------------------------------------------------
extern "C" void kernel_launch(void* const* d_in, const int* in_sizes, int n_in,
                              void* d_out, int out_size)
{
    const float* x     = (const float*)d_in[0];
    const float* W_qkv = (const float*)d_in[1];
    const float* b_qkv = (const float*)d_in[2];
    const float* W_o   = (const float*)d_in[3];
    const float* b_o   = (const float*)d_in[4];
    float* out = (float*)d_out;

    __half *qkv_ptr, *yh_ptr, *xh_ptr, *wtq_ptr, *wto_ptr;
    cudaGetSymbolAddress((void**)&qkv_ptr, g_qkvh);
    cudaGetSymbolAddress((void**)&yh_ptr,  g_yh);
    cudaGetSymbolAddress((void**)&xh_ptr,  g_xh);
    cudaGetSymbolAddress((void**)&wtq_ptr, g_wtq);
    cudaGetSymbolAddress((void**)&wto_ptr, g_wto);

    cudaFuncSetAttribute(gemm_h<true>,  cudaFuncAttributeMaxDynamicSharedMemorySize, GEMM_SMEM);
    cudaFuncSetAttribute(gemm_h<false>, cudaFuncAttributeMaxDynamicSharedMemorySize, GEMM_SMEM);
    cudaFuncSetAttribute(attn_h, cudaFuncAttributeMaxDynamicSharedMemorySize, ATTN_SMEM);

    // Fused prep: convert x + transpose/convert both weight matrices
    prep_all<<<8192, 256>>>(x, W_qkv, W_o, xh_ptr, wtq_ptr, wto_ptr);

    // qkv = half(x @ W_qkv + b_qkv)   [4096, 3072]
    gemm_h<true><<<dim3(QKV_N / BN, MROWS / BM), GTHREADS, GEMM_SMEM>>>(
        xh_ptr, wtq_ptr, b_qkv, qkv_ptr, MROWS, QKV_N, CDIM);

    // y = attention(qkv)  (half out)
    attn_h<<<dim3(TSEQ / AQ, NHEAD, BATCH), 256, ATTN_SMEM>>>(qkv_ptr, yh_ptr);

    // out = y @ W_o + b_o   [4096, 1024] fp32 out
    gemm_h<false><<<dim3(CDIM / BN, MROWS / BM), GTHREADS, GEMM_SMEM>>>(
        yh_ptr, wto_ptr, b_o, out, MROWS, CDIM, CDIM);
}